// round 4
// baseline (speedup 1.0000x reference)
#include <cuda_runtime.h>
#include <cstdint>
#include <math.h>

#define PTS    8192
#define NB     4
#define NSETS  8              // (batch, set): set 0 = yhat, 1 = y
#define NBINS  2048
#define XMIN   (-8.0f)
#define BINW   (16.0f / NBINS)    // 0.0078125
#define INVW   (NBINS / 16.0f)    // 128.0f
#define BLKS_PER 16
#define NQBLK  (NSETS * BLKS_PER) // 128 search blocks
#define PTS4   (PTS + 4)

// Bucket-ordered points: [4 left pads][PTS points][4 right pads].
// .w = lower x-edge of the point's bucket (-1e30 for bucket 0 / left pads).
__device__ float4 g_pts[NSETS][PTS + 8];
__device__ int    g_bstart[NSETS][NBINS];
__device__ float  g_part[NQBLK];

// ---------------------------------------------------------------------------
// prep: per (batch,set) block — histogram by x-bucket, exclusive scan,
// scatter into bucket-ordered g_pts with edge in .w, write bucket starts.
// Within-bucket order is nondeterministic (atomic cursors) but the final
// answer is exact-min based, so the OUTPUT is deterministic.
// ---------------------------------------------------------------------------
__global__ __launch_bounds__(512)
void prep_kernel(const float* __restrict__ yhat, const float* __restrict__ y)
{
    __shared__ int hist[NBINS];
    __shared__ int cursor[NBINS];
    __shared__ int wsum[16];

    const int g = blockIdx.x;          // 0..7
    const int b = g >> 1;
    const float* src = ((g & 1) ? y : yhat) + (size_t)b * PTS * 3;
    const int t = threadIdx.x;

    for (int i = t; i < NBINS; i += 512) hist[i] = 0;
    __syncthreads();

    float3 pt[16]; int bin[16];
#pragma unroll
    for (int j = 0; j < 16; ++j) {
        int i = j * 512 + t;
        float x = src[3 * i], yy = src[3 * i + 1], z = src[3 * i + 2];
        pt[j] = make_float3(x, yy, z);
        int bb = (int)((x - XMIN) * INVW);
        bb = min(max(bb, 0), NBINS - 1);
        bin[j] = bb;
        atomicAdd(&hist[bb], 1);
    }
    __syncthreads();

    // exclusive scan of hist[2048]: 4 bins per thread + 2-level warp scan
    const int base = t * 4;
    int s0 = hist[base], s1 = hist[base + 1], s2 = hist[base + 2], s3 = hist[base + 3];
    int tot = s0 + s1 + s2 + s3;
    const int lane = t & 31, warp = t >> 5;
    int v = tot;
#pragma unroll
    for (int o = 1; o < 32; o <<= 1) {
        int u = __shfl_up_sync(0xffffffffu, v, o);
        if (lane >= o) v += u;
    }
    if (lane == 31) wsum[warp] = v;
    __syncthreads();
    if (warp == 0) {
        int wv = (lane < 16) ? wsum[lane] : 0;
#pragma unroll
        for (int o = 1; o < 16; o <<= 1) {
            int u = __shfl_up_sync(0xffffffffu, wv, o);
            if (lane >= o) wv += u;
        }
        if (lane < 16) wsum[lane] = wv;
    }
    __syncthreads();
    int excl = v - tot + ((warp > 0) ? wsum[warp - 1] : 0);

    int c0 = excl, c1 = excl + s0, c2 = excl + s0 + s1, c3 = excl + s0 + s1 + s2;
    cursor[base] = c0; cursor[base + 1] = c1; cursor[base + 2] = c2; cursor[base + 3] = c3;
    g_bstart[g][base] = c0; g_bstart[g][base + 1] = c1;
    g_bstart[g][base + 2] = c2; g_bstart[g][base + 3] = c3;
    __syncthreads();

    // scatter
#pragma unroll
    for (int j = 0; j < 16; ++j) {
        int pos = atomicAdd(&cursor[bin[j]], 1);
        float edge = (bin[j] == 0) ? -1e30f : (XMIN + bin[j] * BINW);
        g_pts[g][4 + pos] = make_float4(pt[j].x, pt[j].y, pt[j].z, edge);
    }
    // sentinel pads
    if (t < 4)
        g_pts[g][t] = make_float4(-1e30f, 0.f, 0.f, -1e30f);
    else if (t < 8)
        g_pts[g][PTS + t] = make_float4(1e30f, 0.f, 0.f, 1e30f);
}

// ---------------------------------------------------------------------------
// search: warp-cooperative exact NN via outward scan with edge pruning.
// Each warp: 32 consecutive bucket-ordered queries; all lanes process the
// same P point per step (LDS broadcast). Stop when (bucket_edge - qx)^2 >=
// best for every lane (right scan; mirrored for left) — exact because any
// skipped point's x is bounded by its bucket edge.
// ---------------------------------------------------------------------------
__device__ __forceinline__ float dist2(float4 p, float qx, float qy, float qz) {
    float dx = p.x - qx, dy = p.y - qy, dz = p.z - qz;
    return dx * dx + dy * dy + dz * dz;
}

__global__ __launch_bounds__(512)
void search_kernel()
{
    extern __shared__ float4 sp[];   // PTS + 8 entries
    const int bid = blockIdx.x;
    const int grp = bid / BLKS_PER;  // (b, dir) 0..7
    const int sub = bid % BLKS_PER;
    const int qset = grp;
    const int pset = grp ^ 1;        // other set, same batch

    const int t = threadIdx.x;
    for (int i = t; i < PTS + 8; i += 512)
        sp[i] = g_pts[pset][i];
    __syncthreads();

    const int warp = t >> 5, lane = t & 31;
    const int qi = (warp * BLKS_PER + sub) * 32 + lane;   // warp-interleaved balance

    float4 q = g_pts[qset][4 + qi];
    const float qx = q.x, qy = q.y, qz = q.z;

    // per-warp scan start: bucket of lane 16's query x
    float cx = __shfl_sync(0xffffffffu, qx, 16);
    int cb = min(max((int)((cx - XMIN) * INVW), 0), NBINS - 1);
    const int k0 = 4 + g_bstart[pset][cb];

    float best = 3.0e38f;

    // right scan (covers [k0, end) incl. the whole start bucket)
    for (int k = k0; k < PTS4; k += 4) {
        float4 p0 = sp[k], p1 = sp[k + 1], p2 = sp[k + 2], p3 = sp[k + 3];
        best = fminf(best, dist2(p0, qx, qy, qz));
        best = fminf(best, dist2(p1, qx, qy, qz));
        best = fminf(best, dist2(p2, qx, qy, qz));
        best = fminf(best, dist2(p3, qx, qy, qz));
        float e = p3.w - qx;   // lower edge gap of furthest processed point
        if (__all_sync(0xffffffffu, (e >= 0.f) && (e * e >= best))) break;
    }
    // left scan (covers [0, k0))
    for (int k = k0 - 1; k >= 3; k -= 4) {
        float4 p0 = sp[k], p1 = sp[k - 1], p2 = sp[k - 2], p3 = sp[k - 3];
        best = fminf(best, dist2(p0, qx, qy, qz));
        best = fminf(best, dist2(p1, qx, qy, qz));
        best = fminf(best, dist2(p2, qx, qy, qz));
        best = fminf(best, dist2(p3, qx, qy, qz));
        float e = qx - (p3.w + BINW);  // upper edge gap of earliest processed
        if (__all_sync(0xffffffffu, (e >= 0.f) && (e * e >= best))) break;
    }

    // block sum of mins (deterministic: fixed lanes, fixed values)
#pragma unroll
    for (int o = 16; o > 0; o >>= 1)
        best += __shfl_down_sync(0xffffffffu, best, o);
    __shared__ float bsum[16];
    if (lane == 0) bsum[warp] = best;
    __syncthreads();
    if (t == 0) {
        float s = 0.f;
#pragma unroll
        for (int w = 0; w < 16; ++w) s += bsum[w];
        g_part[bid] = s;
    }
}

// loss = sum(all 2*B*PTS mins) / (B*PTS);  out = sqrt(0.5 * loss)
__global__ void final_kernel(float* __restrict__ out)
{
    const int t = threadIdx.x;   // 128
    double s = (double)g_part[t];
#pragma unroll
    for (int o = 16; o > 0; o >>= 1)
        s += __shfl_down_sync(0xffffffffu, s, o);
    __shared__ double sh[4];
    if ((t & 31) == 0) sh[t >> 5] = s;
    __syncthreads();
    if (t == 0) {
        double tot = sh[0] + sh[1] + sh[2] + sh[3];
        out[0] = (float)sqrt(0.5 * tot / (double)(NB * PTS));
    }
}

extern "C" void kernel_launch(void* const* d_in, const int* in_sizes, int n_in,
                              void* d_out, int out_size)
{
    const float* yhat = (const float*)d_in[0];   // [B, N, 3]
    const float* y    = (const float*)d_in[1];   // [B, M, 3]
    (void)in_sizes; (void)n_in; (void)out_size;

    cudaFuncSetAttribute(search_kernel,
                         cudaFuncAttributeMaxDynamicSharedMemorySize,
                         (PTS + 8) * (int)sizeof(float4));

    prep_kernel<<<NSETS, 512>>>(yhat, y);
    search_kernel<<<NQBLK, 512, (PTS + 8) * sizeof(float4)>>>();
    final_kernel<<<1, 128>>>((float*)d_out);
}

// round 5
// speedup vs baseline: 1.5368x; 1.5368x over previous
#include <cuda_runtime.h>
#include <cstdint>
#include <math.h>

#define PTS    8192
#define NB     4
#define NSETS  8              // (batch, set): set 0 = yhat, 1 = y
#define NBINS  2048
#define XMIN   (-8.0f)
#define BINW   (16.0f / NBINS)    // 0.0078125
#define INVW   (NBINS / 16.0f)    // 128.0f
#define PAD    128
#define ARR    (PTS + 2 * PAD)    // 8448
#define BLKS_PER 16
#define NQBLK  (NSETS * BLKS_PER) // 128 search blocks

// Bucket-ordered points: [PAD pads][PTS points][PAD pads].
// .w = |p|^2 for real points; pads are (0,0,0,3e38) so they never win a min.
__device__ float4 g_pts[NSETS][ARR];
__device__ int    g_bstart[NSETS][NBINS + 1];   // [NBINS] = PTS sentinel
__device__ float  g_part[NQBLK];

// ---------------------------------------------------------------------------
// prep: per (batch,set) block — histogram by x-bucket, exclusive scan,
// scatter into bucket-ordered g_pts with |p|^2 in .w, write bucket starts.
// ---------------------------------------------------------------------------
__global__ __launch_bounds__(512)
void prep_kernel(const float* __restrict__ yhat, const float* __restrict__ y)
{
    __shared__ int hist[NBINS];
    __shared__ int cursor[NBINS];
    __shared__ int wsum[16];

    const int g = blockIdx.x;          // 0..7
    const int b = g >> 1;
    const float* src = ((g & 1) ? y : yhat) + (size_t)b * PTS * 3;
    const int t = threadIdx.x;

    for (int i = t; i < NBINS; i += 512) hist[i] = 0;
    __syncthreads();

    float3 pt[16]; int bin[16];
#pragma unroll
    for (int j = 0; j < 16; ++j) {
        int i = j * 512 + t;
        float x = src[3 * i], yy = src[3 * i + 1], z = src[3 * i + 2];
        pt[j] = make_float3(x, yy, z);
        int bb = (int)((x - XMIN) * INVW);
        bb = min(max(bb, 0), NBINS - 1);
        bin[j] = bb;
        atomicAdd(&hist[bb], 1);
    }
    __syncthreads();

    // exclusive scan of hist[2048]: 4 bins per thread + 2-level warp scan
    const int base = t * 4;
    int s0 = hist[base], s1 = hist[base + 1], s2 = hist[base + 2], s3 = hist[base + 3];
    int tot = s0 + s1 + s2 + s3;
    const int lane = t & 31, warp = t >> 5;
    int v = tot;
#pragma unroll
    for (int o = 1; o < 32; o <<= 1) {
        int u = __shfl_up_sync(0xffffffffu, v, o);
        if (lane >= o) v += u;
    }
    if (lane == 31) wsum[warp] = v;
    __syncthreads();
    if (warp == 0) {
        int wv = (lane < 16) ? wsum[lane] : 0;
#pragma unroll
        for (int o = 1; o < 16; o <<= 1) {
            int u = __shfl_up_sync(0xffffffffu, wv, o);
            if (lane >= o) wv += u;
        }
        if (lane < 16) wsum[lane] = wv;
    }
    __syncthreads();
    int excl = v - tot + ((warp > 0) ? wsum[warp - 1] : 0);

    int c0 = excl, c1 = excl + s0, c2 = excl + s0 + s1, c3 = excl + s0 + s1 + s2;
    cursor[base] = c0; cursor[base + 1] = c1; cursor[base + 2] = c2; cursor[base + 3] = c3;
    g_bstart[g][base] = c0; g_bstart[g][base + 1] = c1;
    g_bstart[g][base + 2] = c2; g_bstart[g][base + 3] = c3;
    if (t == 0) g_bstart[g][NBINS] = PTS;
    __syncthreads();

    // scatter (within-bucket order nondeterministic; final min is exact, so
    // the OUTPUT is order-independent)
#pragma unroll
    for (int j = 0; j < 16; ++j) {
        int pos = atomicAdd(&cursor[bin[j]], 1);
        float s = pt[j].x * pt[j].x + pt[j].y * pt[j].y + pt[j].z * pt[j].z;
        g_pts[g][PAD + pos] = make_float4(pt[j].x, pt[j].y, pt[j].z, s);
    }
    // sentinel pads: never win a min, safe to read
    if (t < PAD) {
        float4 padv = make_float4(0.f, 0.f, 0.f, 3.0e38f);
        g_pts[g][t]             = padv;
        g_pts[g][PAD + PTS + t] = padv;
    }
}

// ---------------------------------------------------------------------------
// search: warp-cooperative exact NN, vote-free fixed-trip scans.
//   bestm tracks min over m of (|p|^2 - 2 q.p); true d^2 = bestm + |q|^2.
//   Phase 1: fixed +/-128 points around bucket start k0.
//   Window:  r = sqrt(max_lane clamp(best1+|q|^2,0)); bucket range from
//            [qx_min - r, qx_max + r] — any excluded point has x-gap > r
//            >= sqrt(true best) for every lane, so it cannot win. Exact.
//   Phase 2: fixed-trip scan of the remaining window, no votes.
// ---------------------------------------------------------------------------
__global__ __launch_bounds__(512)
void search_kernel()
{
    extern __shared__ float4 sp[];   // ARR entries
    const int bid = blockIdx.x;
    const int grp = bid / BLKS_PER;  // (b, dir) 0..7
    const int sub = bid % BLKS_PER;
    const int qset = grp;
    const int pset = grp ^ 1;        // other set, same batch

    const int t = threadIdx.x;
    for (int i = t; i < ARR; i += 512)
        sp[i] = g_pts[pset][i];
    __syncthreads();

    const int warp = t >> 5, lane = t & 31;
    const int qi = (warp * BLKS_PER + sub) * 32 + lane;

    float4 q = g_pts[qset][PAD + qi];
    const float qx = q.x;
    const float m2x = -2.f * q.x, m2y = -2.f * q.y, m2z = -2.f * q.z;
    const float sqq = q.w;

    // per-warp scan start: bucket of lane 16's query x
    float cx = __shfl_sync(0xffffffffu, qx, 16);
    int cb = min(max((int)((cx - XMIN) * INVW), 0), NBINS - 1);
    const int k0 = PAD + g_bstart[pset][cb];

    float bestA = 3.0e38f, bestB = 3.0e38f;

#define PROC4(baseidx) do {                                              \
        int _k = (baseidx);                                              \
        float4 p0 = sp[_k], p1 = sp[_k + 1], p2 = sp[_k + 2], p3 = sp[_k + 3]; \
        float d0 = fmaf(m2z, p0.z, fmaf(m2y, p0.y, fmaf(m2x, p0.x, p0.w))); \
        float d1 = fmaf(m2z, p1.z, fmaf(m2y, p1.y, fmaf(m2x, p1.x, p1.w))); \
        float d2 = fmaf(m2z, p2.z, fmaf(m2y, p2.y, fmaf(m2x, p2.x, p2.w))); \
        float d3 = fmaf(m2z, p3.z, fmaf(m2y, p3.y, fmaf(m2x, p3.x, p3.w))); \
        bestA = fminf(bestA, d0); bestB = fminf(bestB, d1);              \
        bestA = fminf(bestA, d2); bestB = fminf(bestB, d3);              \
    } while (0)

    // ---- phase 1: fixed +/-128 points, straight-line ----
#pragma unroll 4
    for (int g4 = 0; g4 < 32; ++g4) PROC4(k0 + 4 * g4);
#pragma unroll 4
    for (int g4 = 0; g4 < 32; ++g4) PROC4(k0 - 4 - 4 * g4);

    // ---- window from phase-1 best ----
    float r2 = fmaxf(fminf(bestA, bestB) + sqq, 0.f);
    float xmn = qx, xmx = qx;
#pragma unroll
    for (int o = 16; o > 0; o >>= 1) {
        r2  = fmaxf(r2,  __shfl_xor_sync(0xffffffffu, r2,  o));
        xmn = fminf(xmn, __shfl_xor_sync(0xffffffffu, xmn, o));
        xmx = fmaxf(xmx, __shfl_xor_sync(0xffffffffu, xmx, o));
    }
    float r = sqrtf(r2);
    int bl = min(max((int)((xmn - r - XMIN) * INVW), 0), NBINS - 1);
    int br = min(max((int)((xmx + r - XMIN) * INVW), 0), NBINS - 1);
    const int istart = PAD + g_bstart[pset][bl];
    const int iend   = PAD + g_bstart[pset][br + 1];

    // ---- phase 2: fixed-trip, vote-free (overshoot into phase-1 range or
    //      pads is harmless: min is idempotent, pads can't win) ----
#pragma unroll 4
    for (int k = istart; k < k0 - 128; k += 4) PROC4(k);
#pragma unroll 4
    for (int k = k0 + 128; k < iend; k += 4) PROC4(k);

    float best = fmaxf(fminf(bestA, bestB) + sqq, 0.f);

    // block sum of mins (deterministic set of values)
#pragma unroll
    for (int o = 16; o > 0; o >>= 1)
        best += __shfl_down_sync(0xffffffffu, best, o);
    __shared__ float bsum[16];
    if (lane == 0) bsum[warp] = best;
    __syncthreads();
    if (t == 0) {
        float s = 0.f;
#pragma unroll
        for (int w = 0; w < 16; ++w) s += bsum[w];
        g_part[bid] = s;
    }
}

// loss = sum(all 2*B*PTS mins) / (B*PTS);  out = sqrt(0.5 * loss)
__global__ void final_kernel(float* __restrict__ out)
{
    const int t = threadIdx.x;   // 128
    double s = (double)g_part[t];
#pragma unroll
    for (int o = 16; o > 0; o >>= 1)
        s += __shfl_down_sync(0xffffffffu, s, o);
    __shared__ double sh[4];
    if ((t & 31) == 0) sh[t >> 5] = s;
    __syncthreads();
    if (t == 0) {
        double tot = sh[0] + sh[1] + sh[2] + sh[3];
        out[0] = (float)sqrt(0.5 * tot / (double)(NB * PTS));
    }
}

extern "C" void kernel_launch(void* const* d_in, const int* in_sizes, int n_in,
                              void* d_out, int out_size)
{
    const float* yhat = (const float*)d_in[0];   // [B, N, 3]
    const float* y    = (const float*)d_in[1];   // [B, M, 3]
    (void)in_sizes; (void)n_in; (void)out_size;

    cudaFuncSetAttribute(search_kernel,
                         cudaFuncAttributeMaxDynamicSharedMemorySize,
                         ARR * (int)sizeof(float4));

    prep_kernel<<<NSETS, 512>>>(yhat, y);
    search_kernel<<<NQBLK, 512, ARR * sizeof(float4)>>>();
    final_kernel<<<1, 128>>>((float*)d_out);
}